// round 1
// baseline (speedup 1.0000x reference)
#include <cuda_runtime.h>
#include <cstdint>

#define N_NODES 100000
#define CH      128
#define N_REL   16
#define N_EDGES 200000
#define K_TOT   (CH + N_REL * CH)   /* 2176 */
#define AGG_LD  (N_REL * CH)        /* 2048 */

// ---------------- device scratch (no allocations allowed) ----------------
__device__ float          g_agg[(size_t)N_NODES * AGG_LD];   // 819.2 MB
__device__ int            g_idx32[N_REL * 2 * N_EDGES];      // 25.6 MB
__device__ unsigned char  g_mask[N_REL * N_EDGES];           // 3.2 MB
__device__ int            g_deg[N_REL * N_NODES];            // 6.4 MB
__device__ float          g_invdeg[N_REL * N_NODES];         // 6.4 MB
__device__ float          g_B[K_TOT * CH];                   // 1.1 MB (tf32-rounded weights)
__device__ int            g_flags[2];                        // [0]=idx is int64, [1]=mask is int32

// ---------------- dtype detection (jax int64/bool layout may vary) -------
__global__ void k_detect(const unsigned int* __restrict__ w,
                         const unsigned char* __restrict__ mb) {
    __shared__ int s64, s32;
    if (threadIdx.x == 0) { s64 = 0; s32 = 0; }
    __syncthreads();
    // If indices are int64 (values < 100000), every odd 32-bit word is 0.
    if (threadIdx.x < 128) {
        if (w[2 * threadIdx.x + 1] != 0u) atomicAdd(&s64, 1);
    }
    // If mask is 4-byte (all-true data), bytes at i%4 != 0 are 0.
    if (threadIdx.x < 192) {
        int i = (threadIdx.x / 3) * 4 + 1 + (threadIdx.x % 3);
        if (mb[i] != 0) atomicAdd(&s32, 1);
    }
    __syncthreads();
    if (threadIdx.x == 0) {
        g_flags[0] = (s64 < 8);   // odd words ~all zero -> int64
        g_flags[1] = (s32 < 8);   // unaligned bytes ~all zero -> int32 mask
    }
}

__global__ void k_cvt_idx(const void* __restrict__ p) {
    int i = blockIdx.x * blockDim.x + threadIdx.x;
    if (i >= N_REL * 2 * N_EDGES) return;
    if (g_flags[0]) g_idx32[i] = (int)((const long long*)p)[i];
    else            g_idx32[i] = ((const int*)p)[i];
}

__global__ void k_cvt_mask(const void* __restrict__ p) {
    int i = blockIdx.x * blockDim.x + threadIdx.x;
    if (i >= N_REL * N_EDGES) return;
    if (g_flags[1]) g_mask[i] = (((const int*)p)[i] != 0);
    else            g_mask[i] = ((const unsigned char*)p)[i];
}

// ---------------- zero agg + deg ----------------
__global__ void k_zero() {
    size_t n4 = (size_t)N_NODES * AGG_LD / 4;
    float4 z = make_float4(0.f, 0.f, 0.f, 0.f);
    size_t stride = (size_t)gridDim.x * blockDim.x;
    for (size_t i = (size_t)blockIdx.x * blockDim.x + threadIdx.x; i < n4; i += stride)
        ((float4*)g_agg)[i] = z;
    int nd = N_REL * N_NODES;
    for (int i = blockIdx.x * blockDim.x + threadIdx.x; i < nd; i += (int)stride)
        g_deg[i] = 0;
}

// ---------------- degree count ----------------
__global__ void k_deg() {
    int e = blockIdx.x * blockDim.x + threadIdx.x;
    int rel = blockIdx.y;
    if (e >= N_EDGES) return;
    if (!g_mask[rel * N_EDGES + e]) return;
    int dst = g_idx32[rel * 2 * N_EDGES + N_EDGES + e];
    atomicAdd(&g_deg[rel * N_NODES + dst], 1);
}

__global__ void k_invdeg() {
    int i = blockIdx.x * blockDim.x + threadIdx.x;
    if (i >= N_REL * N_NODES) return;
    int d = g_deg[i];
    g_invdeg[i] = d > 0 ? 1.0f / (float)d : 0.0f;
}

// ---------------- round weights to tf32 (removes truncation bias) -------
__device__ __forceinline__ unsigned f2tf(float f) {
    unsigned r;
    asm("cvt.rna.tf32.f32 %0, %1;" : "=r"(r) : "f"(f));
    return r;
}

__global__ void k_roundB(const float* __restrict__ selfw, const float* __restrict__ relw) {
    int i = blockIdx.x * blockDim.x + threadIdx.x;
    if (i >= K_TOT * CH) return;
    float v = (i < CH * CH) ? selfw[i] : relw[i - CH * CH];
    g_B[i] = __uint_as_float(f2tf(v));
}

// ---------------- scatter: agg[dst, rel*128+c] += x[src,c] * invdeg -----
__global__ void k_scatter(const float* __restrict__ x) {
    int rel = blockIdx.y;
    int e = blockIdx.x * 8 + (threadIdx.x >> 5);
    int lane = threadIdx.x & 31;
    if (!g_mask[rel * N_EDGES + e]) return;
    const int* ip = g_idx32 + rel * 2 * N_EDGES;
    int src = ip[e];
    int dst = ip[N_EDGES + e];
    float s = g_invdeg[rel * N_NODES + dst];
    float4 v = ((const float4*)(x + (size_t)src * CH))[lane];
    float* a = g_agg + (size_t)dst * AGG_LD + rel * CH + lane * 4;
    atomicAdd(a + 0, v.x * s);
    atomicAdd(a + 1, v.y * s);
    atomicAdd(a + 2, v.z * s);
    atomicAdd(a + 3, v.w * s);
}

// ---------------- GEMM: out[100000,128] = [x|AGG] @ g_B  (tf32 mma) -----
#define AS 36    /* A smem row stride (floats): banks (4r+c)%32 -> conflict-free frags */
#define BS 136   /* B smem row stride: banks (8k+n)%32 -> conflict-free frags */

__device__ __forceinline__ void cp16(float* sdst, const float* gsrc, int bytes) {
    unsigned s = (unsigned)__cvta_generic_to_shared(sdst);
    asm volatile("cp.async.cg.shared.global [%0], [%1], 16, %2;\n"
                 :: "r"(s), "l"(gsrc), "r"(bytes));
}

__global__ __launch_bounds__(256, 2) void k_gemm(const float* __restrict__ x,
                                                 float* __restrict__ out) {
    extern __shared__ float sm[];
    float* sA = sm;                 // 2 stages * 128*AS
    float* sB = sm + 2 * 128 * AS;  // 2 stages * 32*BS
    int tid = threadIdx.x;
    int warp = tid >> 5, lane = tid & 31;
    int wm = warp >> 2, wn = warp & 3;   // 2x4 warp grid, warp tile 64x32
    int bM = blockIdx.x * 128;

    float c[4][4][4];
#pragma unroll
    for (int i = 0; i < 4; i++)
#pragma unroll
        for (int j = 0; j < 4; j++)
#pragma unroll
            for (int k = 0; k < 4; k++) c[i][j][k] = 0.f;

    const int NK = K_TOT / 32;   // 68

    auto load_stage = [&](int kt, int stage) {
        float* dA = sA + stage * 128 * AS;
        float* dB = sB + stage * 32 * BS;
#pragma unroll
        for (int i = 0; i < 4; i++) {
            int idx = tid + 256 * i;
            int row = idx >> 3, c4 = idx & 7;     // A tile 128 x 8 float4
            int rg = bM + row;
            int k = kt * 32 + c4 * 4;
            const float* src;
            if (kt < 4) src = x + (size_t)rg * CH + k;
            else        src = g_agg + (size_t)rg * AGG_LD + (k - CH);
            int ok = (rg < N_NODES) ? 16 : 0;
            cp16(dA + row * AS + c4 * 4, ok ? src : x, ok);
        }
#pragma unroll
        for (int i = 0; i < 4; i++) {
            int idx = tid + 256 * i;
            int kr = idx >> 5, c4 = idx & 31;     // B tile 32 x 32 float4
            cp16(dB + kr * BS + c4 * 4, g_B + (size_t)(kt * 32 + kr) * CH + c4 * 4, 16);
        }
        asm volatile("cp.async.commit_group;\n");
    };

    load_stage(0, 0);

    for (int kt = 0; kt < NK; kt++) {
        int stage = kt & 1;
        if (kt + 1 < NK) {
            load_stage(kt + 1, stage ^ 1);
            asm volatile("cp.async.wait_group 1;\n");
        } else {
            asm volatile("cp.async.wait_group 0;\n");
        }
        __syncthreads();

        const float* A = sA + stage * 128 * AS + (wm * 64) * AS;
        const float* B = sB + stage * 32 * BS + wn * 32;
#pragma unroll
        for (int ks = 0; ks < 4; ks++) {
            unsigned a[4][4], b[4][2];
            int col = ks * 8 + (lane & 3);
            int r = (lane >> 2);
#pragma unroll
            for (int mf = 0; mf < 4; mf++) {
                const float* Ap = A + (mf * 16 + r) * AS + col;
                a[mf][0] = f2tf(Ap[0]);
                a[mf][1] = f2tf(Ap[8 * AS]);
                a[mf][2] = f2tf(Ap[4]);
                a[mf][3] = f2tf(Ap[8 * AS + 4]);
            }
            int kr = ks * 8 + (lane & 3);
#pragma unroll
            for (int nf = 0; nf < 4; nf++) {
                const float* Bp = B + kr * BS + nf * 8 + (lane >> 2);
                b[nf][0] = __float_as_uint(Bp[0]);       // g_B pre-rounded to tf32
                b[nf][1] = __float_as_uint(Bp[4 * BS]);
            }
#pragma unroll
            for (int mf = 0; mf < 4; mf++)
#pragma unroll
                for (int nf = 0; nf < 4; nf++)
                    asm volatile(
                        "mma.sync.aligned.m16n8k8.row.col.f32.tf32.tf32.f32 "
                        "{%0,%1,%2,%3},{%4,%5,%6,%7},{%8,%9},{%0,%1,%2,%3};\n"
                        : "+f"(c[mf][nf][0]), "+f"(c[mf][nf][1]),
                          "+f"(c[mf][nf][2]), "+f"(c[mf][nf][3])
                        : "r"(a[mf][0]), "r"(a[mf][1]), "r"(a[mf][2]), "r"(a[mf][3]),
                          "r"(b[nf][0]), "r"(b[nf][1]));
        }
        __syncthreads();
    }

    // epilogue: direct store (full result, no accumulation needed)
#pragma unroll
    for (int mf = 0; mf < 4; mf++) {
        int r0 = bM + wm * 64 + mf * 16 + (lane >> 2);
#pragma unroll
        for (int nf = 0; nf < 4; nf++) {
            int cc = wn * 32 + nf * 8 + (lane & 3) * 2;
            if (r0 < N_NODES)
                *(float2*)(out + (size_t)r0 * CH + cc) = make_float2(c[mf][nf][0], c[mf][nf][1]);
            if (r0 + 8 < N_NODES)
                *(float2*)(out + (size_t)(r0 + 8) * CH + cc) = make_float2(c[mf][nf][2], c[mf][nf][3]);
        }
    }
}

// ---------------- launch ----------------
extern "C" void kernel_launch(void* const* d_in, const int* in_sizes, int n_in,
                              void* d_out, int out_size) {
    const float* x     = (const float*)d_in[0];
    const void*  idx   = d_in[1];
    const void*  mask  = d_in[2];
    const float* selfw = (const float*)d_in[3];
    const float* relw  = (const float*)d_in[4];
    float* out = (float*)d_out;

    k_detect<<<1, 256>>>((const unsigned int*)idx, (const unsigned char*)mask);
    k_cvt_idx<<<(N_REL * 2 * N_EDGES + 255) / 256, 256>>>(idx);
    k_cvt_mask<<<(N_REL * N_EDGES + 255) / 256, 256>>>(mask);
    k_zero<<<8192, 256>>>();
    k_deg<<<dim3((N_EDGES + 255) / 256, N_REL), 256>>>();
    k_invdeg<<<(N_REL * N_NODES + 255) / 256, 256>>>();
    k_roundB<<<(K_TOT * CH + 255) / 256, 256>>>(selfw, relw);
    k_scatter<<<dim3(N_EDGES / 8, N_REL), 256>>>(x);

    static int smem_set = 0;
    size_t smem = (2 * 128 * AS + 2 * 32 * BS) * sizeof(float); // 71680 B
    if (!smem_set) {
        cudaFuncSetAttribute(k_gemm, cudaFuncAttributeMaxDynamicSharedMemorySize, (int)smem);
        smem_set = 1;
    }
    k_gemm<<<(N_NODES + 127) / 128, 256, smem>>>(x, out);
}